// round 2
// baseline (speedup 1.0000x reference)
#include <cuda_runtime.h>

#define THRESH 0.3f
#define MARGIN 0.1f
#define WEIGHT 0.1f

constexpr int NBLOCKS  = 1184;   // 148 SMs x 8 CTAs -> single wave
constexpr int NTHREADS = 256;

// Scratch for deterministic fused reduction (no device allocation allowed).
__device__ float        g_psum[NBLOCKS];
__device__ unsigned int g_pcnt[NBLOCKS];
__device__ unsigned int g_ticket;   // zero-initialized; last block resets it

__device__ __forceinline__ void row_accum(float4 p, float t,
                                          float& sum, unsigned int& cnt)
{
    float p4 = p.y, p5 = p.z, p6 = p.w;

    bool a = p4 > THRESH;
    bool b = p5 > THRESH;
    bool c = p6 > THRESH;
    bool m45  = a && b;
    bool m56  = b && c;
    bool m456 = m45 && c;

    // exactly as reference: relu(MARGIN - (p5*t - p4*t)) etc.
    float term45 = fmaxf(MARGIN - (p5 * t - p4 * t), 0.0f);
    float term56 = fmaxf(MARGIN - (p6 * t - p5 * t), 0.0f);
    float d45 = fabsf(p5 - p4);
    float d56 = fabsf(p6 - p5);
    float termO = fmaxf(d45 - d56 + MARGIN, 0.0f);

    sum += m45  ? term45 : 0.0f;
    sum += m56  ? term56 : 0.0f;
    sum += m456 ? termO  : 0.0f;
    cnt += (unsigned)m45 + (unsigned)m56 + (unsigned)m456;
}

__global__ __launch_bounds__(NTHREADS)
void tcl_fused(const float4* __restrict__ pred,    // (B,4) as float4 rows
               const float4* __restrict__ times4,  // (B,) viewed as float4
               float* __restrict__ out,
               int B4)                              // B / 4
{
    float        sum = 0.0f;
    unsigned int cnt = 0;

    const int stride = gridDim.x * blockDim.x;
    int j = blockIdx.x * blockDim.x + threadIdx.x;

    // 4 rows per iteration: 1x LDG.128 times + 4x LDG.128 pred (high MLP)
    for (; j < B4; j += stride) {
        float4 tv = times4[j];
        float4 p0 = pred[4 * j + 0];
        float4 p1 = pred[4 * j + 1];
        float4 p2 = pred[4 * j + 2];
        float4 p3 = pred[4 * j + 3];
        row_accum(p0, tv.x, sum, cnt);
        row_accum(p1, tv.y, sum, cnt);
        row_accum(p2, tv.z, sum, cnt);
        row_accum(p3, tv.w, sum, cnt);
    }

    // Block reduction
    #pragma unroll
    for (int off = 16; off > 0; off >>= 1) {
        sum += __shfl_down_sync(0xFFFFFFFFu, sum, off);
        cnt += __shfl_down_sync(0xFFFFFFFFu, cnt, off);
    }

    __shared__ float        s_sum[NTHREADS / 32];
    __shared__ unsigned int s_cnt[NTHREADS / 32];
    __shared__ bool         s_last;
    int lane = threadIdx.x & 31;
    int wid  = threadIdx.x >> 5;
    if (lane == 0) { s_sum[wid] = sum; s_cnt[wid] = cnt; }
    __syncthreads();

    if (wid == 0) {
        sum = (lane < NTHREADS / 32) ? s_sum[lane] : 0.0f;
        cnt = (lane < NTHREADS / 32) ? s_cnt[lane] : 0u;
        #pragma unroll
        for (int off = 4; off > 0; off >>= 1) {
            sum += __shfl_down_sync(0xFFFFFFFFu, sum, off);
            cnt += __shfl_down_sync(0xFFFFFFFFu, cnt, off);
        }
        if (lane == 0) {
            g_psum[blockIdx.x] = sum;
            g_pcnt[blockIdx.x] = cnt;
            __threadfence();
            unsigned int ticket = atomicAdd(&g_ticket, 1u);
            s_last = (ticket == (unsigned)gridDim.x - 1u);
        }
    }
    __syncthreads();

    // Last block to finish reduces all partials (deterministic values).
    if (s_last) {
        float        fsum = 0.0f;
        unsigned int fcnt = 0;
        for (int i = threadIdx.x; i < NBLOCKS; i += NTHREADS) {
            fsum += g_psum[i];
            fcnt += g_pcnt[i];
        }
        #pragma unroll
        for (int off = 16; off > 0; off >>= 1) {
            fsum += __shfl_down_sync(0xFFFFFFFFu, fsum, off);
            fcnt += __shfl_down_sync(0xFFFFFFFFu, fcnt, off);
        }
        if (lane == 0) { s_sum[wid] = fsum; s_cnt[wid] = fcnt; }
        __syncthreads();
        if (wid == 0) {
            fsum = (lane < NTHREADS / 32) ? s_sum[lane] : 0.0f;
            fcnt = (lane < NTHREADS / 32) ? s_cnt[lane] : 0u;
            #pragma unroll
            for (int off = 4; off > 0; off >>= 1) {
                fsum += __shfl_down_sync(0xFFFFFFFFu, fsum, off);
                fcnt += __shfl_down_sync(0xFFFFFFFFu, fcnt, off);
            }
            if (lane == 0) {
                float count = (float)fcnt;
                float loss  = (count > 0.0f) ? (fsum / fmaxf(count, 1.0f)) : fsum;
                out[0] = WEIGHT * loss;
                g_ticket = 0u;   // reset for next graph replay
            }
        }
    }
}

extern "C" void kernel_launch(void* const* d_in, const int* in_sizes, int n_in,
                              void* d_out, int out_size)
{
    const float4* pred   = (const float4*)d_in[0];  // (B,4) float32
    const float4* times4 = (const float4*)d_in[1];  // (B,1) float32, B % 4 == 0
    float*        out    = (float*)d_out;

    int B  = in_sizes[1];   // element count of relative_times = B
    int B4 = B >> 2;        // B = 8388608 -> divisible by 4

    tcl_fused<<<NBLOCKS, NTHREADS>>>(pred, times4, out, B4);
}

// round 3
// speedup vs baseline: 1.2600x; 1.2600x over previous
#include <cuda_runtime.h>

#define THRESH 0.3f
#define MARGIN 0.1f
#define WEIGHT 0.1f

constexpr int NBLOCKS  = 1024;   // 2^18 threads -> B=2^23 divides exactly (32 rows/thread)
constexpr int NTHREADS = 256;

// Scratch for deterministic fused reduction (no device allocation allowed).
__device__ float        g_psum[NBLOCKS];
__device__ unsigned int g_pcnt[NBLOCKS];
__device__ unsigned int g_ticket;   // zero-init; last block resets after use

__device__ __forceinline__ void row_accum(float4 p, float t,
                                          float& sum, unsigned int& cnt)
{
    float p4 = p.y, p5 = p.z, p6 = p.w;

    bool a = p4 > THRESH;
    bool b = p5 > THRESH;
    bool c = p6 > THRESH;
    bool m45  = a && b;
    bool m56  = b && c;
    bool m456 = m45 && c;

    // exactly as reference: relu(MARGIN - (p5*t - p4*t)) etc.
    float term45 = fmaxf(MARGIN - (p5 * t - p4 * t), 0.0f);
    float term56 = fmaxf(MARGIN - (p6 * t - p5 * t), 0.0f);
    float d45 = fabsf(p5 - p4);
    float d56 = fabsf(p6 - p5);
    float termO = fmaxf(d45 - d56 + MARGIN, 0.0f);

    sum += m45  ? term45 : 0.0f;
    sum += m56  ? term56 : 0.0f;
    sum += m456 ? termO  : 0.0f;
    cnt += (unsigned)m45 + (unsigned)m56 + (unsigned)m456;
}

__global__ __launch_bounds__(NTHREADS)
void tcl_fused(const float4* __restrict__ pred,   // (B,4) as float4 rows
               const float*  __restrict__ times,  // (B,)
               float* __restrict__ out,
               int B)
{
    float        sum = 0.0f;
    unsigned int cnt = 0;

    const int S   = gridDim.x * blockDim.x;        // 262144
    const int idx = blockIdx.x * blockDim.x + threadIdx.x;

    // Stride-partitioned 4-way unroll: every load warp-coalesced,
    // 8 independent loads in flight per iteration.
    int i = idx;
    for (; i + 3 * S < B; i += 4 * S) {
        float4 p0 = __ldcs(&pred[i]);
        float4 p1 = __ldcs(&pred[i + S]);
        float4 p2 = __ldcs(&pred[i + 2 * S]);
        float4 p3 = __ldcs(&pred[i + 3 * S]);
        float  t0 = __ldcs(&times[i]);
        float  t1 = __ldcs(&times[i + S]);
        float  t2 = __ldcs(&times[i + 2 * S]);
        float  t3 = __ldcs(&times[i + 3 * S]);
        row_accum(p0, t0, sum, cnt);
        row_accum(p1, t1, sum, cnt);
        row_accum(p2, t2, sum, cnt);
        row_accum(p3, t3, sum, cnt);
    }
    for (; i < B; i += S) {
        float4 p = __ldcs(&pred[i]);
        float  t = __ldcs(&times[i]);
        row_accum(p, t, sum, cnt);
    }

    // Block reduction
    #pragma unroll
    for (int off = 16; off > 0; off >>= 1) {
        sum += __shfl_down_sync(0xFFFFFFFFu, sum, off);
        cnt += __shfl_down_sync(0xFFFFFFFFu, cnt, off);
    }

    __shared__ float        s_sum[NTHREADS / 32];
    __shared__ unsigned int s_cnt[NTHREADS / 32];
    __shared__ bool         s_last;
    int lane = threadIdx.x & 31;
    int wid  = threadIdx.x >> 5;
    if (lane == 0) { s_sum[wid] = sum; s_cnt[wid] = cnt; }
    __syncthreads();

    if (wid == 0) {
        sum = (lane < NTHREADS / 32) ? s_sum[lane] : 0.0f;
        cnt = (lane < NTHREADS / 32) ? s_cnt[lane] : 0u;
        #pragma unroll
        for (int off = 4; off > 0; off >>= 1) {
            sum += __shfl_down_sync(0xFFFFFFFFu, sum, off);
            cnt += __shfl_down_sync(0xFFFFFFFFu, cnt, off);
        }
        if (lane == 0) {
            g_psum[blockIdx.x] = sum;
            g_pcnt[blockIdx.x] = cnt;
            __threadfence();
            unsigned int ticket = atomicAdd(&g_ticket, 1u);
            s_last = (ticket == (unsigned)gridDim.x - 1u);
        }
    }
    __syncthreads();

    // Last block reduces all partials (values deterministic regardless of order).
    if (s_last) {
        float        fsum = 0.0f;
        unsigned int fcnt = 0;
        for (int k = threadIdx.x; k < NBLOCKS; k += NTHREADS) {
            fsum += g_psum[k];
            fcnt += g_pcnt[k];
        }
        #pragma unroll
        for (int off = 16; off > 0; off >>= 1) {
            fsum += __shfl_down_sync(0xFFFFFFFFu, fsum, off);
            fcnt += __shfl_down_sync(0xFFFFFFFFu, fcnt, off);
        }
        if (lane == 0) { s_sum[wid] = fsum; s_cnt[wid] = fcnt; }
        __syncthreads();
        if (wid == 0) {
            fsum = (lane < NTHREADS / 32) ? s_sum[lane] : 0.0f;
            fcnt = (lane < NTHREADS / 32) ? s_cnt[lane] : 0u;
            #pragma unroll
            for (int off = 4; off > 0; off >>= 1) {
                fsum += __shfl_down_sync(0xFFFFFFFFu, fsum, off);
                fcnt += __shfl_down_sync(0xFFFFFFFFu, fcnt, off);
            }
            if (lane == 0) {
                float count = (float)fcnt;
                float loss  = (count > 0.0f) ? (fsum / fmaxf(count, 1.0f)) : fsum;
                out[0] = WEIGHT * loss;
                g_ticket = 0u;   // reset for next graph replay
            }
        }
    }
}

extern "C" void kernel_launch(void* const* d_in, const int* in_sizes, int n_in,
                              void* d_out, int out_size)
{
    const float4* pred  = (const float4*)d_in[0];  // (B,4) float32
    const float*  times = (const float*)d_in[1];   // (B,1) float32
    float*        out   = (float*)d_out;

    int B = in_sizes[1];   // element count of relative_times = B

    tcl_fused<<<NBLOCKS, NTHREADS>>>(pred, times, out, B);
}